// round 10
// baseline (speedup 1.0000x reference)
#include <cuda_runtime.h>
#include <cuda_bf16.h>
#include <cstdint>
#include <math.h>

// Problem constants (fixed by the dataset)
#define BB 2
#define SS 2048
#define DD 512
#define HH 8
#define DH 64
#define BH (BB*HH)          // 16
#define MAXK 32
#define EPSF 1e-8f

// ---------------- scratch (static device globals; no allocs allowed) --------
__device__ float        g_q  [BB*HH*SS*DH];   // [B,H,S,64] fp32
__device__ float        g_kT [BB*HH*DH*SS];   // [B,H,64,S] fp32 (exact rescue)
__device__ __nv_bfloat16 g_kb[BB*HH*SS*DH];   // [B,H,S,64] bf16 (mma B operand)
__device__ float        g_v  [BB*HH*SS*DH];   // [B,H,S,64]
__device__ float        g_attn[BB*SS*DD];     // [B,S,D]

// ---------------- warp reduce helpers ---------------------------------------
__device__ __forceinline__ float warpMaxF(float v){
#pragma unroll
    for (int o = 16; o; o >>= 1) v = fmaxf(v, __shfl_xor_sync(0xffffffffu, v, o));
    return v;
}
__device__ __forceinline__ float warpSumF(float v){
#pragma unroll
    for (int o = 16; o; o >>= 1) v += __shfl_xor_sync(0xffffffffu, v, o);
    return v;
}
__device__ __forceinline__ unsigned warpMaxU(unsigned v){
#pragma unroll
    for (int o = 16; o; o >>= 1) { unsigned t = __shfl_xor_sync(0xffffffffu, v, o); v = t > v ? t : v; }
    return v;
}
__device__ __forceinline__ int warpSumI(int v){
#pragma unroll
    for (int o = 16; o; o >>= 1) v += __shfl_xor_sync(0xffffffffu, v, o);
    return v;
}
__device__ __forceinline__ unsigned ordf(float f){
    unsigned u = __float_as_uint(f);
    return (u & 0x80000000u) ? ~u : (u | 0x80000000u);
}

// bf16 mma m16n8k16: D = A(16x16,row) * B(16x8,col) + C, fp32 accum
__device__ __forceinline__ void mma16816(float c[4], const unsigned a[4],
                                         unsigned b0, unsigned b1){
    asm volatile(
        "mma.sync.aligned.m16n8k16.row.col.f32.bf16.bf16.f32 "
        "{%0,%1,%2,%3}, {%4,%5,%6,%7}, {%8,%9}, {%0,%1,%2,%3};"
        : "+f"(c[0]), "+f"(c[1]), "+f"(c[2]), "+f"(c[3])
        : "r"(a[0]), "r"(a[1]), "r"(a[2]), "r"(a[3]), "r"(b0), "r"(b1));
}

// ---------------- SGEMM: C[M,N] = A[M,K] * Bw[N,K]^T + bias ------------------
// BM=128 x BN=64 tiles, double-buffered, 3 CTAs/SM (R8-proven).
// MODE 0: plain store. MODE 1: q/kT/kb/v scatter.
template<int MODE>
__global__ __launch_bounds__(256, 3)
void sgemm_nt(const float* __restrict__ A, const float* __restrict__ Bw,
              const float* __restrict__ bias, float* __restrict__ C,
              int M, int N, int K)
{
    const int BM = 128, BN = 64, BK = 16;
    __shared__ float As[2][BK][BM + 4];
    __shared__ float Bs[2][BK][BN + 4];

    int tid = threadIdx.x;
    int tx = tid & 15, ty = tid >> 4;
    int bm = blockIdx.y * BM, bn = blockIdx.x * BN;

    int arow0 = tid >> 2, ac = (tid & 3) * 4;
    int arow1 = arow0 + 64;
    int brow  = tid >> 2, bc = ac;

    float acc[8][4];
#pragma unroll
    for (int i = 0; i < 8; i++)
#pragma unroll
        for (int j = 0; j < 4; j++) acc[i][j] = 0.f;

    const float* Ab = A + (size_t)bm * K;
    const float* Bb = Bw + (size_t)bn * K;

    float4 pa0, pa1, pb0;

    pa0 = *(const float4*)(Ab + (size_t)arow0 * K + ac);
    pa1 = *(const float4*)(Ab + (size_t)arow1 * K + ac);
    pb0 = *(const float4*)(Bb + (size_t)brow  * K + bc);
    As[0][ac+0][arow0]=pa0.x; As[0][ac+1][arow0]=pa0.y; As[0][ac+2][arow0]=pa0.z; As[0][ac+3][arow0]=pa0.w;
    As[0][ac+0][arow1]=pa1.x; As[0][ac+1][arow1]=pa1.y; As[0][ac+2][arow1]=pa1.z; As[0][ac+3][arow1]=pa1.w;
    Bs[0][bc+0][brow ]=pb0.x; Bs[0][bc+1][brow ]=pb0.y; Bs[0][bc+2][brow ]=pb0.z; Bs[0][bc+3][brow ]=pb0.w;
    __syncthreads();

    for (int k0 = 0; k0 < K; k0 += BK) {
        int buf = (k0 >> 4) & 1;
        bool more = (k0 + BK) < K;
        if (more) {
            int kn = k0 + BK;
            pa0 = *(const float4*)(Ab + (size_t)arow0 * K + kn + ac);
            pa1 = *(const float4*)(Ab + (size_t)arow1 * K + kn + ac);
            pb0 = *(const float4*)(Bb + (size_t)brow  * K + kn + bc);
        }
#pragma unroll
        for (int k = 0; k < BK; k++) {
            float4 a0 = *(const float4*)&As[buf][k][ty * 8];
            float4 a1 = *(const float4*)&As[buf][k][ty * 8 + 4];
            float4 b0 = *(const float4*)&Bs[buf][k][tx * 4];
            float av[8] = {a0.x,a0.y,a0.z,a0.w,a1.x,a1.y,a1.z,a1.w};
            float bv[4] = {b0.x,b0.y,b0.z,b0.w};
#pragma unroll
            for (int i = 0; i < 8; i++)
#pragma unroll
                for (int j = 0; j < 4; j++) acc[i][j] = fmaf(av[i], bv[j], acc[i][j]);
        }
        if (more) {
            int nb = buf ^ 1;
            As[nb][ac+0][arow0]=pa0.x; As[nb][ac+1][arow0]=pa0.y; As[nb][ac+2][arow0]=pa0.z; As[nb][ac+3][arow0]=pa0.w;
            As[nb][ac+0][arow1]=pa1.x; As[nb][ac+1][arow1]=pa1.y; As[nb][ac+2][arow1]=pa1.z; As[nb][ac+3][arow1]=pa1.w;
            Bs[nb][bc+0][brow ]=pb0.x; Bs[nb][bc+1][brow ]=pb0.y; Bs[nb][bc+2][brow ]=pb0.z; Bs[nb][bc+3][brow ]=pb0.w;
        }
        __syncthreads();
    }

    if (MODE == 0) {
#pragma unroll
        for (int i = 0; i < 8; i++) {
            int mrow = bm + ty * 8 + i;
            int col = bn + tx * 4;
            float4 bv = *(const float4*)(bias + col);
            float4 o;
            o.x = acc[i][0] + bv.x; o.y = acc[i][1] + bv.y;
            o.z = acc[i][2] + bv.z; o.w = acc[i][3] + bv.w;
            *(float4*)(C + (size_t)mrow * N + col) = o;
        }
    } else {
#pragma unroll
        for (int i = 0; i < 8; i++) {
            int mrow = bm + ty * 8 + i;
            int b = mrow >> 11;          // S = 2048
            int s = mrow & 2047;
#pragma unroll
            for (int j = 0; j < 4; j++) {
                int n = bn + tx * 4 + j;
                float val = acc[i][j] + bias[n];
                int sec = n >> 9;        // 0:q 1:k 2:v (D = 512)
                int nn  = n & 511;
                int head = nn >> 6, d = nn & 63;
                size_t sd = ((size_t)((b*HH+head)*SS) + s)*DH + d;
                if (sec == 0) {
                    g_q[sd] = val;
                } else if (sec == 1) {
                    g_kT[((size_t)((b*HH+head)*DH) + d)*SS + s] = val;
                    g_kb[sd] = __float2bfloat16(val);
                } else {
                    g_v[sd] = val;
                }
            }
        }
    }
}

// ---------------- fused attention v5: tensor-core scores + fp32 rescue -------
// TQ=16 queries/block, 512 threads (16 warps). Phase 1: warp w computes the
// 16x128 score slab for cols [128w,128w+128) via bf16 mma.sync m16n8k16
// (fp32 accum), scaled and stored to smem. Phase 2 (warp w owns row w):
// approx max -> Z,S1 (entropy identity) + candidate set within MARGIN of max;
// candidates rescued exactly in fp32 (same q,kT data); exact argmax/tie set
// drives the tk=1 fast path. Cold exact fallback for H<1.2 / overflow.
#define TQ 16
#define ATHREADS 512
#define CAP 256
#define MARGIN 0.05f

#define OFF_QF (TQ*SS*4)                 // after s_sc
#define OFF_QB (OFF_QF + TQ*DH*4)
#define OFF_CNT (OFF_QB + TQ*DH*2)
#define OFF_IDX (OFF_CNT + TQ*4)
#define OFF_EXV (OFF_IDX + TQ*CAP*2)
#define ATTN_SMEM (OFF_EXV + TQ*CAP*4)

__global__ __launch_bounds__(ATHREADS, 1)
void attn_kernel()
{
    extern __shared__ unsigned char smem[];
    float* s_sc = (float*)smem;                               // [TQ][2048]
    float* s_qf = (float*)(smem + OFF_QF);                    // [16][64] fp32
    __nv_bfloat16* s_qb = (__nv_bfloat16*)(smem + OFF_QB);    // [16][64] bf16
    int*   s_cnt = (int*)(smem + OFF_CNT);                    // [TQ]
    unsigned short* s_idx = (unsigned short*)(smem + OFF_IDX);// [TQ][CAP]
    float* s_exv = (float*)(smem + OFF_EXV);                  // [TQ][CAP]

    int bh = blockIdx.y;
    int q0 = blockIdx.x * TQ;
    const float* Q  = g_q  + ((size_t)bh * SS + q0) * DH;
    const float* KT = g_kT + (size_t)bh * DH * SS;
    const __nv_bfloat16* Kb = g_kb + (size_t)bh * SS * DH;
    const float* V  = g_v  + (size_t)bh * SS * DH;
    int tid = threadIdx.x;
    int lane = tid & 31, w = tid >> 5;

    // load Q tile fp32 + bf16 copy
    for (int e = tid; e < TQ * DH; e += ATHREADS) {
        float qv = Q[e];
        s_qf[e] = qv;
        s_qb[e] = __float2bfloat16(qv);
    }
    if (tid < TQ) s_cnt[tid] = 0;
    __syncthreads();

    const float scale = 0.125f;   // 1/sqrt(64)

    // ---- phase 1: bf16 mma scores, warp w covers cols [128w,128w+128) -----
    {
        int r4 = lane >> 2, cq = (lane & 3) * 2;
        // A fragments: 4 k-chunks of 16
        unsigned afr[4][4];
#pragma unroll
        for (int kk = 0; kk < 4; kk++) {
            int cb = kk * 16 + cq;
            afr[kk][0] = *(const unsigned*)&s_qb[ r4      * DH + cb    ];
            afr[kk][1] = *(const unsigned*)&s_qb[(r4 + 8) * DH + cb    ];
            afr[kk][2] = *(const unsigned*)&s_qb[ r4      * DH + cb + 8];
            afr[kk][3] = *(const unsigned*)&s_qb[(r4 + 8) * DH + cb + 8];
        }
#pragma unroll 2
        for (int nt = 0; nt < 16; nt++) {
            int n0 = w * 128 + nt * 8;
            const __nv_bfloat16* kb = Kb + (size_t)(n0 + r4) * DH + cq;
            float c[4] = {0.f, 0.f, 0.f, 0.f};
#pragma unroll
            for (int kk = 0; kk < 4; kk++) {
                unsigned b0 = *(const unsigned*)(kb + kk * 16);
                unsigned b1 = *(const unsigned*)(kb + kk * 16 + 8);
                mma16816(c, afr[kk], b0, b1);
            }
            float2 lo; lo.x = c[0] * scale; lo.y = c[1] * scale;
            float2 hi; hi.x = c[2] * scale; hi.y = c[3] * scale;
            *(float2*)&s_sc[ r4      * SS + n0 + cq] = lo;
            *(float2*)&s_sc[(r4 + 8) * SS + n0 + cq] = hi;
        }
    }
    __syncthreads();

    // ---- phase 2: warp w owns row w ----------------------------------------
    float* sc = s_sc + w * SS;

    // sweep 1: approx max
    float m = -3.0e38f;
#pragma unroll 8
    for (int jj = 0; jj < 64; jj++) m = fmaxf(m, sc[lane + (jj << 5)]);
    m = warpMaxF(m);

    // sweep 2: Z, S1, candidate collection (approx scores)
    float thr = m - MARGIN;
    float z = 0.f, s1 = 0.f;
#pragma unroll 4
    for (int jj = 0; jj < 64; jj++) {
        int j = lane + (jj << 5);
        float s = sc[j];
        float x = s - m;
        float p = expf(x);
        z += p;
        s1 = fmaf(p, x, s1);
        if (s >= thr) {
            int pos = atomicAdd(&s_cnt[w], 1);
            if (pos < CAP) s_idx[w * CAP + pos] = (unsigned short)j;
        }
    }
    z  = warpSumF(z);
    s1 = warpSumF(s1);
    float hent = logf(z) - s1 / z;   // approx entropy (error ~1e-3, harmless)
    __syncwarp();
    int cnt = s_cnt[w];

    int b = bh >> 3, hd = bh & 7;
    float* outp = &g_attn[((size_t)(b * SS + q0 + w)) * DD + hd * DH + lane * 2];

    if (hent >= 1.2f && cnt <= CAP) {
        // rescue: exact fp32 scores for candidates; exact argmax + tie set
        const float* qrow = s_qf + w * DH;
        float q_lo = qrow[lane], q_hi = qrow[lane + 32];
        float m_ex = -3.0e38f;
        for (int t = 0; t < cnt; t++) {
            int j = s_idx[w * CAP + t];
            float part = fmaf(q_lo, KT[(size_t)lane * SS + j],
                              q_hi * KT[(size_t)(lane + 32) * SS + j]);
            float s = warpSumF(part) * scale;
            if (lane == 0) s_exv[w * CAP + t] = s;
            m_ex = fmaxf(m_ex, s);
        }
        __syncwarp();
        // ties of exact max: p = 1 each, P = tiecnt
        int tiec = 0;
        float a0 = 0.f, a1 = 0.f;
        int d0 = lane * 2;
        for (int t = 0; t < cnt; t++) {
            if (s_exv[w * CAP + t] == m_ex) {
                tiec++;
                int j = s_idx[w * CAP + t];
                float2 vv = *(const float2*)(V + (size_t)j * DH + d0);
                a0 += vv.x; a1 += vv.y;
            }
        }
        float wgt = 1.0f / ((float)tiec + EPSF * z);
        float2 o; o.x = a0 * wgt; o.y = a1 * wgt;
        *(float2*)outp = o;
    } else {
        // ---- cold exact fallback: full fp32 recompute, reference semantics -
        const float* qrow = s_qf + w * DH;
        float fb[64];
        for (int jj = 0; jj < 64; jj++) {
            int j = lane + (jj << 5);
            float s = 0.f;
            for (int d = 0; d < DH; d++)
                s = fmaf(qrow[d], KT[(size_t)d * SS + j], s);
            fb[jj] = s * scale;
        }
        float m2 = -3.0e38f;
        for (int jj = 0; jj < 64; jj++) m2 = fmaxf(m2, fb[jj]);
        m2 = warpMaxF(m2);
        float z2 = 0.f;
        for (int jj = 0; jj < 64; jj++) z2 += expf(fb[jj] - m2);
        z2 = warpSumF(z2);
        float invZ = 1.0f / z2;
        float he = 0.f;
        for (int jj = 0; jj < 64; jj++) {
            float p  = expf(fb[jj] - m2);
            float ww = p * invZ;
            he -= ww * logf(ww + EPSF);
        }
        he = warpSumF(he);
        int tk = (int)(32.0f * (1.0f - he));
        tk = tk < 1 ? 1 : (tk > MAXK ? MAXK : tk);

        unsigned thr_u;
        if (tk == 1) {
            thr_u = ordf(m2);
        } else {
            thr_u = 0xFFFFFFFFu;
            int removed = 0;
            while (removed < tk) {
                unsigned best = 0u;
                for (int jj = 0; jj < 64; jj++) {
                    unsigned u = ordf(fb[jj]);
                    if (u < thr_u && u > best) best = u;
                }
                best = warpMaxU(best);
                int c = 0;
                for (int jj = 0; jj < 64; jj++) c += (ordf(fb[jj]) == best);
                c = warpSumI(c);
                removed += c;
                thr_u = best;
            }
        }

        float P = 0.f;
        for (int jj = 0; jj < 64; jj++)
            if (ordf(fb[jj]) >= thr_u) P += expf(fb[jj] - m2);
        P = warpSumF(P);
        float invDen = 1.0f / (P + EPSF * z2);

        float r0 = 0.f, r1 = 0.f;
        for (int dd = 0; dd < DH; dd += 2) {
            float a0 = 0.f, a1 = 0.f;
            for (int jj = 0; jj < 64; jj++) {
                float s = fb[jj];
                if (ordf(s) >= thr_u) {
                    int j = lane + (jj << 5);
                    float p = expf(s - m2);
                    float2 vv = *(const float2*)(V + (size_t)j * DH + dd);
                    a0 = fmaf(p, vv.x, a0);
                    a1 = fmaf(p, vv.y, a1);
                }
            }
            a0 = warpSumF(a0);
            a1 = warpSumF(a1);
            if (lane == (dd >> 1)) { r0 = a0; r1 = a1; }
        }
        float2 o; o.x = r0 * invDen; o.y = r1 * invDen;
        *(float2*)outp = o;
    }
}

// ---------------- launch -----------------------------------------------------
extern "C" void kernel_launch(void* const* d_in, const int* in_sizes, int n_in,
                              void* d_out, int out_size)
{
    const float* x     = (const float*)d_in[0];
    const float* w_in  = (const float*)d_in[1];
    const float* b_in  = (const float*)d_in[2];
    const float* w_out = (const float*)d_in[3];
    const float* b_out = (const float*)d_in[4];
    float* out = (float*)d_out;

    float* pattn = nullptr;
    cudaGetSymbolAddress((void**)&pattn, g_attn);

    cudaFuncSetAttribute(attn_kernel,
                         cudaFuncAttributeMaxDynamicSharedMemorySize, ATTN_SMEM);

    // 1) QKV projection with head-layout scatter (768 blocks of 128x64)
    sgemm_nt<1><<<dim3((3*DD)/64, (BB*SS)/128), 256>>>(
        x, w_in, b_in, nullptr, BB*SS, 3*DD, DD);

    // 2) fused attention: tensor-core scores + exact rescue
    attn_kernel<<<dim3(SS/TQ, BH), ATHREADS, ATTN_SMEM>>>();

    // 3) output projection (256 blocks of 128x64)
    sgemm_nt<0><<<dim3(DD/64, (BB*SS)/128), 256>>>(
        pattn, w_out, b_out, out, BB*SS, DD, DD);
}

// round 11
// speedup vs baseline: 1.3258x; 1.3258x over previous
#include <cuda_runtime.h>
#include <cuda_bf16.h>
#include <cstdint>
#include <math.h>

// Problem constants (fixed by the dataset)
#define BB 2
#define SS 2048
#define DD 512
#define HH 8
#define DH 64
#define BH (BB*HH)          // 16
#define MAXK 32
#define EPSF 1e-8f

// ---------------- scratch (static device globals; no allocs allowed) --------
__device__ float        g_q  [BB*HH*SS*DH];   // [B,H,S,64] fp32
__device__ float        g_kT [BB*HH*DH*SS];   // [B,H,64,S] fp32 (exact rescue)
__device__ __nv_bfloat16 g_kb[BB*HH*SS*DH];   // [B,H,S,64] bf16 (mma B operand)
__device__ float        g_v  [BB*HH*SS*DH];   // [B,H,S,64]
__device__ float        g_attn[BB*SS*DD];     // [B,S,D]

// ---------------- warp reduce helpers ---------------------------------------
__device__ __forceinline__ float warpMaxF(float v){
#pragma unroll
    for (int o = 16; o; o >>= 1) v = fmaxf(v, __shfl_xor_sync(0xffffffffu, v, o));
    return v;
}
__device__ __forceinline__ float warpSumF(float v){
#pragma unroll
    for (int o = 16; o; o >>= 1) v += __shfl_xor_sync(0xffffffffu, v, o);
    return v;
}
__device__ __forceinline__ unsigned warpMaxU(unsigned v){
#pragma unroll
    for (int o = 16; o; o >>= 1) { unsigned t = __shfl_xor_sync(0xffffffffu, v, o); v = t > v ? t : v; }
    return v;
}
__device__ __forceinline__ int warpSumI(int v){
#pragma unroll
    for (int o = 16; o; o >>= 1) v += __shfl_xor_sync(0xffffffffu, v, o);
    return v;
}
__device__ __forceinline__ unsigned ordf(float f){
    unsigned u = __float_as_uint(f);
    return (u & 0x80000000u) ? ~u : (u | 0x80000000u);
}
__device__ __forceinline__ float bf16lo(unsigned u){ return __uint_as_float(u << 16); }
__device__ __forceinline__ float bf16hi(unsigned u){ return __uint_as_float(u & 0xffff0000u); }

// bf16 mma m16n8k16: D = A(16x16,row) * B(16x8,col) + C, fp32 accum
__device__ __forceinline__ void mma16816(float c[4], const unsigned a[4],
                                         unsigned b0, unsigned b1){
    asm volatile(
        "mma.sync.aligned.m16n8k16.row.col.f32.bf16.bf16.f32 "
        "{%0,%1,%2,%3}, {%4,%5,%6,%7}, {%8,%9}, {%0,%1,%2,%3};"
        : "+f"(c[0]), "+f"(c[1]), "+f"(c[2]), "+f"(c[3])
        : "r"(a[0]), "r"(a[1]), "r"(a[2]), "r"(a[3]), "r"(b0), "r"(b1));
}

// ---------------- SGEMM: C[M,N] = A[M,K] * Bw[N,K]^T + bias ------------------
// BM=128 x BN=64 tiles, double-buffered, 3 CTAs/SM (R8-proven).
// MODE 0: plain store. MODE 1: q/kT/kb/v scatter.
template<int MODE>
__global__ __launch_bounds__(256, 3)
void sgemm_nt(const float* __restrict__ A, const float* __restrict__ Bw,
              const float* __restrict__ bias, float* __restrict__ C,
              int M, int N, int K)
{
    const int BM = 128, BN = 64, BK = 16;
    __shared__ float As[2][BK][BM + 4];
    __shared__ float Bs[2][BK][BN + 4];

    int tid = threadIdx.x;
    int tx = tid & 15, ty = tid >> 4;
    int bm = blockIdx.y * BM, bn = blockIdx.x * BN;

    int arow0 = tid >> 2, ac = (tid & 3) * 4;
    int arow1 = arow0 + 64;
    int brow  = tid >> 2, bc = ac;

    float acc[8][4];
#pragma unroll
    for (int i = 0; i < 8; i++)
#pragma unroll
        for (int j = 0; j < 4; j++) acc[i][j] = 0.f;

    const float* Ab = A + (size_t)bm * K;
    const float* Bb = Bw + (size_t)bn * K;

    float4 pa0, pa1, pb0;

    pa0 = *(const float4*)(Ab + (size_t)arow0 * K + ac);
    pa1 = *(const float4*)(Ab + (size_t)arow1 * K + ac);
    pb0 = *(const float4*)(Bb + (size_t)brow  * K + bc);
    As[0][ac+0][arow0]=pa0.x; As[0][ac+1][arow0]=pa0.y; As[0][ac+2][arow0]=pa0.z; As[0][ac+3][arow0]=pa0.w;
    As[0][ac+0][arow1]=pa1.x; As[0][ac+1][arow1]=pa1.y; As[0][ac+2][arow1]=pa1.z; As[0][ac+3][arow1]=pa1.w;
    Bs[0][bc+0][brow ]=pb0.x; Bs[0][bc+1][brow ]=pb0.y; Bs[0][bc+2][brow ]=pb0.z; Bs[0][bc+3][brow ]=pb0.w;
    __syncthreads();

    for (int k0 = 0; k0 < K; k0 += BK) {
        int buf = (k0 >> 4) & 1;
        bool more = (k0 + BK) < K;
        if (more) {
            int kn = k0 + BK;
            pa0 = *(const float4*)(Ab + (size_t)arow0 * K + kn + ac);
            pa1 = *(const float4*)(Ab + (size_t)arow1 * K + kn + ac);
            pb0 = *(const float4*)(Bb + (size_t)brow  * K + kn + bc);
        }
#pragma unroll
        for (int k = 0; k < BK; k++) {
            float4 a0 = *(const float4*)&As[buf][k][ty * 8];
            float4 a1 = *(const float4*)&As[buf][k][ty * 8 + 4];
            float4 b0 = *(const float4*)&Bs[buf][k][tx * 4];
            float av[8] = {a0.x,a0.y,a0.z,a0.w,a1.x,a1.y,a1.z,a1.w};
            float bv[4] = {b0.x,b0.y,b0.z,b0.w};
#pragma unroll
            for (int i = 0; i < 8; i++)
#pragma unroll
                for (int j = 0; j < 4; j++) acc[i][j] = fmaf(av[i], bv[j], acc[i][j]);
        }
        if (more) {
            int nb = buf ^ 1;
            As[nb][ac+0][arow0]=pa0.x; As[nb][ac+1][arow0]=pa0.y; As[nb][ac+2][arow0]=pa0.z; As[nb][ac+3][arow0]=pa0.w;
            As[nb][ac+0][arow1]=pa1.x; As[nb][ac+1][arow1]=pa1.y; As[nb][ac+2][arow1]=pa1.z; As[nb][ac+3][arow1]=pa1.w;
            Bs[nb][bc+0][brow ]=pb0.x; Bs[nb][bc+1][brow ]=pb0.y; Bs[nb][bc+2][brow ]=pb0.z; Bs[nb][bc+3][brow ]=pb0.w;
        }
        __syncthreads();
    }

    if (MODE == 0) {
#pragma unroll
        for (int i = 0; i < 8; i++) {
            int mrow = bm + ty * 8 + i;
            int col = bn + tx * 4;
            float4 bv = *(const float4*)(bias + col);
            float4 o;
            o.x = acc[i][0] + bv.x; o.y = acc[i][1] + bv.y;
            o.z = acc[i][2] + bv.z; o.w = acc[i][3] + bv.w;
            *(float4*)(C + (size_t)mrow * N + col) = o;
        }
    } else {
#pragma unroll
        for (int i = 0; i < 8; i++) {
            int mrow = bm + ty * 8 + i;
            int b = mrow >> 11;          // S = 2048
            int s = mrow & 2047;
#pragma unroll
            for (int j = 0; j < 4; j++) {
                int n = bn + tx * 4 + j;
                float val = acc[i][j] + bias[n];
                int sec = n >> 9;        // 0:q 1:k 2:v (D = 512)
                int nn  = n & 511;
                int head = nn >> 6, d = nn & 63;
                size_t sd = ((size_t)((b*HH+head)*SS) + s)*DH + d;
                if (sec == 0) {
                    g_q[sd] = val;
                } else if (sec == 1) {
                    g_kT[((size_t)((b*HH+head)*DH) + d)*SS + s] = val;
                    g_kb[sd] = __float2bfloat16(val);
                } else {
                    g_v[sd] = val;
                }
            }
        }
    }
}

// ---------------- fused attention v6: smem-staged mma + bf16 scores ----------
// TQ=16 queries, 512 threads (16 warps). K processed in 16 chunks of 128 cols:
// cooperative coalesced staging to s_kb[128][72] (pad 72 -> conflict-free
// fragment LDS), warp w runs the m16n8k16 mma for its 8-col tile, scores
// stored bf16 to s_sc[16][2056] (pad -> conflict-free stores). Phase 2 (warp w
// owns row w): approx max -> Z,S1 (entropy identity) + candidates within
// MARGIN; exact fp32 rescue of candidates gives the true argmax/tie set
// (validated in R10). Cold exact fallback for H<1.2 / overflow.
#define TQ 16
#define ATHREADS 512
#define CAP 128
#define MARGIN 0.05f
#define SROW 2056                        // bf16 per score row (2048 + 8 pad)
#define KROW 72                          // bf16 per staged K row (64 + 8 pad)

#define OFF_KB  (TQ*SROW*2)              // 65792
#define OFF_QB  (OFF_KB + 128*KROW*2)    // + 18432
#define OFF_QF  (OFF_QB + TQ*DH*2)       // + 2048
#define OFF_CNT (OFF_QF + TQ*DH*4)       // + 4096
#define OFF_IDX (OFF_CNT + 64)
#define OFF_EXV (OFF_IDX + TQ*CAP*2)
#define ATTN_SMEM (OFF_EXV + TQ*CAP*4)   // = 102720 bytes

__global__ __launch_bounds__(ATHREADS, 2)
void attn_kernel()
{
    extern __shared__ unsigned char smem[];
    unsigned short* s_sc = (unsigned short*)smem;             // [16][SROW]
    __nv_bfloat16* s_kb = (__nv_bfloat16*)(smem + OFF_KB);    // [128][KROW]
    __nv_bfloat16* s_qb = (__nv_bfloat16*)(smem + OFF_QB);    // [16][64]
    float* s_qf = (float*)(smem + OFF_QF);                    // [16][64]
    int*   s_cnt = (int*)(smem + OFF_CNT);                    // [16]
    unsigned short* s_idx = (unsigned short*)(smem + OFF_IDX);// [16][CAP]
    float* s_exv = (float*)(smem + OFF_EXV);                  // [16][CAP]

    int bh = blockIdx.y;
    int q0 = blockIdx.x * TQ;
    const float* Q  = g_q  + ((size_t)bh * SS + q0) * DH;
    const float* KT = g_kT + (size_t)bh * DH * SS;
    const __nv_bfloat16* Kb = g_kb + (size_t)bh * SS * DH;
    const float* V  = g_v  + (size_t)bh * SS * DH;
    int tid = threadIdx.x;
    int lane = tid & 31, w = tid >> 5;

    // load Q tile fp32 + bf16 copy
    for (int e = tid; e < TQ * DH; e += ATHREADS) {
        float qv = Q[e];
        s_qf[e] = qv;
        s_qb[e] = __float2bfloat16(qv);
    }
    if (tid < TQ) s_cnt[tid] = 0;
    __syncthreads();

    const float scale = 0.125f;   // 1/sqrt(64)
    int r4 = lane >> 2, cq = (lane & 3) * 2;

    // A fragments (Q), persistent across chunks
    unsigned afr[4][4];
#pragma unroll
    for (int kk = 0; kk < 4; kk++) {
        int cb = kk * 16 + cq;
        afr[kk][0] = *(const unsigned*)&s_qb[ r4      * DH + cb    ];
        afr[kk][1] = *(const unsigned*)&s_qb[(r4 + 8) * DH + cb    ];
        afr[kk][2] = *(const unsigned*)&s_qb[ r4      * DH + cb + 8];
        afr[kk][3] = *(const unsigned*)&s_qb[(r4 + 8) * DH + cb + 8];
    }

    // ---- phase 1: 16 chunks of 128 K-rows ----------------------------------
    for (int ch = 0; ch < 16; ch++) {
        // coalesced staging: 1024 float4, 2 per thread
        {
            int f = tid;
#pragma unroll
            for (int rpt = 0; rpt < 2; rpt++, f += ATHREADS) {
                int row = f >> 3, c8 = f & 7;
                float4 v = *(const float4*)(Kb + ((size_t)(ch * 128 + row)) * DH + c8 * 8);
                *(float4*)((char*)s_kb + row * (KROW*2) + c8 * 16) = v;
            }
        }
        __syncthreads();
        // warp w: mma for cols n0..n0+7
        {
            float c[4] = {0.f, 0.f, 0.f, 0.f};
            const __nv_bfloat16* kbp = s_kb + (w * 8 + r4) * KROW + cq;
#pragma unroll
            for (int kk = 0; kk < 4; kk++) {
                unsigned b0 = *(const unsigned*)(kbp + kk * 16);
                unsigned b1 = *(const unsigned*)(kbp + kk * 16 + 8);
                mma16816(c, afr[kk], b0, b1);
            }
            int n0 = ch * 128 + w * 8;
            __nv_bfloat162 lo = __floats2bfloat162_rn(c[0] * scale, c[1] * scale);
            __nv_bfloat162 hi = __floats2bfloat162_rn(c[2] * scale, c[3] * scale);
            *(__nv_bfloat162*)&s_sc[ r4      * SROW + n0 + cq] = lo;
            *(__nv_bfloat162*)&s_sc[(r4 + 8) * SROW + n0 + cq] = hi;
        }
        __syncthreads();
    }

    // ---- phase 2: warp w owns row w ----------------------------------------
    const unsigned* scrow = (const unsigned*)(s_sc + w * SROW);  // 1024 u32

    float m = -3.0e38f;
#pragma unroll 8
    for (int jj = 0; jj < 32; jj++) {
        unsigned u = scrow[lane + (jj << 5)];
        m = fmaxf(m, fmaxf(bf16lo(u), bf16hi(u)));
    }
    m = warpMaxF(m);

    float thr = m - MARGIN;
    float z = 0.f, s1 = 0.f;
#pragma unroll 4
    for (int jj = 0; jj < 32; jj++) {
        int wi = lane + (jj << 5);
        unsigned u = scrow[wi];
        float a = bf16lo(u), bvv = bf16hi(u);
        float xa = a - m, xb = bvv - m;
        float pa = expf(xa), pb = expf(xb);
        z += pa + pb;
        s1 = fmaf(pa, xa, fmaf(pb, xb, s1));
        if (a >= thr) {
            int pos = atomicAdd(&s_cnt[w], 1);
            if (pos < CAP) s_idx[w * CAP + pos] = (unsigned short)(wi * 2);
        }
        if (bvv >= thr) {
            int pos = atomicAdd(&s_cnt[w], 1);
            if (pos < CAP) s_idx[w * CAP + pos] = (unsigned short)(wi * 2 + 1);
        }
    }
    z  = warpSumF(z);
    s1 = warpSumF(s1);
    float hent = logf(z) - s1 / z;   // approx entropy (tiny error, harmless)
    __syncwarp();
    int cnt = s_cnt[w];

    int b = bh >> 3, hd = bh & 7;
    float* outp = &g_attn[((size_t)(b * SS + q0 + w)) * DD + hd * DH + lane * 2];

    if (hent >= 1.2f && cnt <= CAP) {
        // rescue: exact fp32 scores for candidates; exact argmax + tie set
        const float* qrow = s_qf + w * DH;
        float q_lo = qrow[lane], q_hi = qrow[lane + 32];
        float m_ex = -3.0e38f;
        for (int t = 0; t < cnt; t++) {
            int j = s_idx[w * CAP + t];
            float part = fmaf(q_lo, KT[(size_t)lane * SS + j],
                              q_hi * KT[(size_t)(lane + 32) * SS + j]);
            float s = warpSumF(part) * scale;
            if (lane == 0) s_exv[w * CAP + t] = s;
            m_ex = fmaxf(m_ex, s);
        }
        __syncwarp();
        int tiec = 0;
        float a0 = 0.f, a1 = 0.f;
        int d0 = lane * 2;
        for (int t = 0; t < cnt; t++) {
            if (s_exv[w * CAP + t] == m_ex) {
                tiec++;
                int j = s_idx[w * CAP + t];
                float2 vv = *(const float2*)(V + (size_t)j * DH + d0);
                a0 += vv.x; a1 += vv.y;
            }
        }
        float wgt = 1.0f / ((float)tiec + EPSF * z);
        float2 o; o.x = a0 * wgt; o.y = a1 * wgt;
        *(float2*)outp = o;
    } else {
        // ---- cold exact fallback: full fp32 recompute, reference semantics -
        const float* qrow = s_qf + w * DH;
        float fb[64];
        for (int jj = 0; jj < 64; jj++) {
            int j = lane + (jj << 5);
            float s = 0.f;
            for (int d = 0; d < DH; d++)
                s = fmaf(qrow[d], KT[(size_t)d * SS + j], s);
            fb[jj] = s * scale;
        }
        float m2 = -3.0e38f;
        for (int jj = 0; jj < 64; jj++) m2 = fmaxf(m2, fb[jj]);
        m2 = warpMaxF(m2);
        float z2 = 0.f;
        for (int jj = 0; jj < 64; jj++) z2 += expf(fb[jj] - m2);
        z2 = warpSumF(z2);
        float invZ = 1.0f / z2;
        float he = 0.f;
        for (int jj = 0; jj < 64; jj++) {
            float p  = expf(fb[jj] - m2);
            float ww = p * invZ;
            he -= ww * logf(ww + EPSF);
        }
        he = warpSumF(he);
        int tk = (int)(32.0f * (1.0f - he));
        tk = tk < 1 ? 1 : (tk > MAXK ? MAXK : tk);

        unsigned thr_u;
        if (tk == 1) {
            thr_u = ordf(m2);
        } else {
            thr_u = 0xFFFFFFFFu;
            int removed = 0;
            while (removed < tk) {
                unsigned best = 0u;
                for (int jj = 0; jj < 64; jj++) {
                    unsigned u = ordf(fb[jj]);
                    if (u < thr_u && u > best) best = u;
                }
                best = warpMaxU(best);
                int c = 0;
                for (int jj = 0; jj < 64; jj++) c += (ordf(fb[jj]) == best);
                c = warpSumI(c);
                removed += c;
                thr_u = best;
            }
        }

        float P = 0.f;
        for (int jj = 0; jj < 64; jj++)
            if (ordf(fb[jj]) >= thr_u) P += expf(fb[jj] - m2);
        P = warpSumF(P);
        float invDen = 1.0f / (P + EPSF * z2);

        float r0 = 0.f, r1 = 0.f;
        for (int dd = 0; dd < DH; dd += 2) {
            float a0 = 0.f, a1 = 0.f;
            for (int jj = 0; jj < 64; jj++) {
                float s = fb[jj];
                if (ordf(s) >= thr_u) {
                    int j = lane + (jj << 5);
                    float p = expf(s - m2);
                    float2 vv = *(const float2*)(V + (size_t)j * DH + dd);
                    a0 = fmaf(p, vv.x, a0);
                    a1 = fmaf(p, vv.y, a1);
                }
            }
            a0 = warpSumF(a0);
            a1 = warpSumF(a1);
            if (lane == (dd >> 1)) { r0 = a0; r1 = a1; }
        }
        float2 o; o.x = r0 * invDen; o.y = r1 * invDen;
        *(float2*)outp = o;
    }
}

// ---------------- launch -----------------------------------------------------
extern "C" void kernel_launch(void* const* d_in, const int* in_sizes, int n_in,
                              void* d_out, int out_size)
{
    const float* x     = (const float*)d_in[0];
    const float* w_in  = (const float*)d_in[1];
    const float* b_in  = (const float*)d_in[2];
    const float* w_out = (const float*)d_in[3];
    const float* b_out = (const float*)d_in[4];
    float* out = (float*)d_out;

    float* pattn = nullptr;
    cudaGetSymbolAddress((void**)&pattn, g_attn);

    cudaFuncSetAttribute(attn_kernel,
                         cudaFuncAttributeMaxDynamicSharedMemorySize, ATTN_SMEM);

    // 1) QKV projection with head-layout scatter (768 blocks of 128x64)
    sgemm_nt<1><<<dim3((3*DD)/64, (BB*SS)/128), 256>>>(
        x, w_in, b_in, nullptr, BB*SS, 3*DD, DD);

    // 2) fused attention: smem-staged tensor-core scores + exact rescue
    attn_kernel<<<dim3(SS/TQ, BH), ATHREADS, ATTN_SMEM>>>();

    // 3) output projection (256 blocks of 128x64)
    sgemm_nt<0><<<dim3(DD/64, (BB*SS)/128), 256>>>(
        pattn, w_out, b_out, out, BB*SS, DD, DD);
}

// round 13
// speedup vs baseline: 1.3874x; 1.0465x over previous
#include <cuda_runtime.h>
#include <cuda_bf16.h>
#include <cstdint>
#include <math.h>

// Problem constants (fixed by the dataset)
#define BB 2
#define SS 2048
#define DD 512
#define HH 8
#define DH 64
#define BH (BB*HH)          // 16
#define MAXK 32
#define EPSF 1e-8f

// ---------------- scratch (static device globals; no allocs allowed) --------
__device__ float        g_q  [BB*HH*SS*DH];   // [B,H,S,64] fp32
__device__ float        g_kT [BB*HH*DH*SS];   // [B,H,64,S] fp32 (exact rescue)
__device__ __nv_bfloat16 g_kb[BB*HH*SS*DH];   // [B,H,S,64] bf16 (mma B operand)
__device__ float        g_v  [BB*HH*SS*DH];   // [B,H,S,64]
__device__ float        g_attn[BB*SS*DD];     // [B,S,D]

// ---------------- warp reduce helpers ---------------------------------------
__device__ __forceinline__ float warpMaxF(float v){
#pragma unroll
    for (int o = 16; o; o >>= 1) v = fmaxf(v, __shfl_xor_sync(0xffffffffu, v, o));
    return v;
}
__device__ __forceinline__ float warpSumF(float v){
#pragma unroll
    for (int o = 16; o; o >>= 1) v += __shfl_xor_sync(0xffffffffu, v, o);
    return v;
}
__device__ __forceinline__ unsigned warpMaxU(unsigned v){
#pragma unroll
    for (int o = 16; o; o >>= 1) { unsigned t = __shfl_xor_sync(0xffffffffu, v, o); v = t > v ? t : v; }
    return v;
}
__device__ __forceinline__ int warpSumI(int v){
#pragma unroll
    for (int o = 16; o; o >>= 1) v += __shfl_xor_sync(0xffffffffu, v, o);
    return v;
}
__device__ __forceinline__ unsigned ordf(float f){
    unsigned u = __float_as_uint(f);
    return (u & 0x80000000u) ? ~u : (u | 0x80000000u);
}
__device__ __forceinline__ float bf16lo(unsigned u){ return __uint_as_float(u << 16); }
__device__ __forceinline__ float bf16hi(unsigned u){ return __uint_as_float(u & 0xffff0000u); }

// bf16 mma m16n8k16: D = A(16x16,row) * B(16x8,col) + C, fp32 accum
__device__ __forceinline__ void mma16816(float c[4], const unsigned a[4],
                                         unsigned b0, unsigned b1){
    asm volatile(
        "mma.sync.aligned.m16n8k16.row.col.f32.bf16.bf16.f32 "
        "{%0,%1,%2,%3}, {%4,%5,%6,%7}, {%8,%9}, {%0,%1,%2,%3};"
        : "+f"(c[0]), "+f"(c[1]), "+f"(c[2]), "+f"(c[3])
        : "r"(a[0]), "r"(a[1]), "r"(a[2]), "r"(a[3]), "r"(b0), "r"(b1));
}

// ---------------- SGEMM: C[M,N] = A[M,K] * Bw[N,K]^T + bias ------------------
// BM=128 x BN=64 tiles, double-buffered, 3 CTAs/SM (R8-proven).
// MODE 0: plain store. MODE 1: q/kT/kb/v scatter.
template<int MODE>
__global__ __launch_bounds__(256, 3)
void sgemm_nt(const float* __restrict__ A, const float* __restrict__ Bw,
              const float* __restrict__ bias, float* __restrict__ C,
              int M, int N, int K)
{
    const int BM = 128, BN = 64, BK = 16;
    __shared__ float As[2][BK][BM + 4];
    __shared__ float Bs[2][BK][BN + 4];

    int tid = threadIdx.x;
    int tx = tid & 15, ty = tid >> 4;
    int bm = blockIdx.y * BM, bn = blockIdx.x * BN;

    int arow0 = tid >> 2, ac = (tid & 3) * 4;
    int arow1 = arow0 + 64;
    int brow  = tid >> 2, bc = ac;

    float acc[8][4];
#pragma unroll
    for (int i = 0; i < 8; i++)
#pragma unroll
        for (int j = 0; j < 4; j++) acc[i][j] = 0.f;

    const float* Ab = A + (size_t)bm * K;
    const float* Bb = Bw + (size_t)bn * K;

    float4 pa0, pa1, pb0;

    pa0 = *(const float4*)(Ab + (size_t)arow0 * K + ac);
    pa1 = *(const float4*)(Ab + (size_t)arow1 * K + ac);
    pb0 = *(const float4*)(Bb + (size_t)brow  * K + bc);
    As[0][ac+0][arow0]=pa0.x; As[0][ac+1][arow0]=pa0.y; As[0][ac+2][arow0]=pa0.z; As[0][ac+3][arow0]=pa0.w;
    As[0][ac+0][arow1]=pa1.x; As[0][ac+1][arow1]=pa1.y; As[0][ac+2][arow1]=pa1.z; As[0][ac+3][arow1]=pa1.w;
    Bs[0][bc+0][brow ]=pb0.x; Bs[0][bc+1][brow ]=pb0.y; Bs[0][bc+2][brow ]=pb0.z; Bs[0][bc+3][brow ]=pb0.w;
    __syncthreads();

    for (int k0 = 0; k0 < K; k0 += BK) {
        int buf = (k0 >> 4) & 1;
        bool more = (k0 + BK) < K;
        if (more) {
            int kn = k0 + BK;
            pa0 = *(const float4*)(Ab + (size_t)arow0 * K + kn + ac);
            pa1 = *(const float4*)(Ab + (size_t)arow1 * K + kn + ac);
            pb0 = *(const float4*)(Bb + (size_t)brow  * K + kn + bc);
        }
#pragma unroll
        for (int k = 0; k < BK; k++) {
            float4 a0 = *(const float4*)&As[buf][k][ty * 8];
            float4 a1 = *(const float4*)&As[buf][k][ty * 8 + 4];
            float4 b0 = *(const float4*)&Bs[buf][k][tx * 4];
            float av[8] = {a0.x,a0.y,a0.z,a0.w,a1.x,a1.y,a1.z,a1.w};
            float bv[4] = {b0.x,b0.y,b0.z,b0.w};
#pragma unroll
            for (int i = 0; i < 8; i++)
#pragma unroll
                for (int j = 0; j < 4; j++) acc[i][j] = fmaf(av[i], bv[j], acc[i][j]);
        }
        if (more) {
            int nb = buf ^ 1;
            As[nb][ac+0][arow0]=pa0.x; As[nb][ac+1][arow0]=pa0.y; As[nb][ac+2][arow0]=pa0.z; As[nb][ac+3][arow0]=pa0.w;
            As[nb][ac+0][arow1]=pa1.x; As[nb][ac+1][arow1]=pa1.y; As[nb][ac+2][arow1]=pa1.z; As[nb][ac+3][arow1]=pa1.w;
            Bs[nb][bc+0][brow ]=pb0.x; Bs[nb][bc+1][brow ]=pb0.y; Bs[nb][bc+2][brow ]=pb0.z; Bs[nb][bc+3][brow ]=pb0.w;
        }
        __syncthreads();
    }

    if (MODE == 0) {
#pragma unroll
        for (int i = 0; i < 8; i++) {
            int mrow = bm + ty * 8 + i;
            int col = bn + tx * 4;
            float4 bv = *(const float4*)(bias + col);
            float4 o;
            o.x = acc[i][0] + bv.x; o.y = acc[i][1] + bv.y;
            o.z = acc[i][2] + bv.z; o.w = acc[i][3] + bv.w;
            *(float4*)(C + (size_t)mrow * N + col) = o;
        }
    } else {
#pragma unroll
        for (int i = 0; i < 8; i++) {
            int mrow = bm + ty * 8 + i;
            int b = mrow >> 11;          // S = 2048
            int s = mrow & 2047;
#pragma unroll
            for (int j = 0; j < 4; j++) {
                int n = bn + tx * 4 + j;
                float val = acc[i][j] + bias[n];
                int sec = n >> 9;        // 0:q 1:k 2:v (D = 512)
                int nn  = n & 511;
                int head = nn >> 6, d = nn & 63;
                size_t sd = ((size_t)((b*HH+head)*SS) + s)*DH + d;
                if (sec == 0) {
                    g_q[sd] = val;
                } else if (sec == 1) {
                    g_kT[((size_t)((b*HH+head)*DH) + d)*SS + s] = val;
                    g_kb[sd] = __float2bfloat16(val);
                } else {
                    g_v[sd] = val;
                }
            }
        }
    }
}

// ---------------- fused attention v7: pipelined smem-staged mma --------------
// Like v6 (R11-proven numerics) but phase-1 staging is double-buffered with
// distance-2 register prefetch, 1 barrier per 128-row chunk (16 vs 32), LDG
// latency hidden behind mma+STS. s_qf dropped (rescue/fallback read g_q),
// CAP 128->64; smem 110.9KB -> still 2 CTAs/SM.
#define TQ 16
#define ATHREADS 512
#define CAP 64
#define MARGIN 0.05f
#define SROW 2056                        // bf16 per score row (2048 + 8 pad)
#define KROW 72                          // bf16 per staged K row (64 + 8 pad)

#define OFF_KB0 (TQ*SROW*2)              // 65792
#define OFF_KB1 (OFF_KB0 + 128*KROW*2)   // + 18432
#define OFF_QB  (OFF_KB1 + 128*KROW*2)   // + 18432
#define OFF_CNT (OFF_QB + TQ*DH*2)       // + 2048
#define OFF_IDX (OFF_CNT + 64)
#define OFF_EXV (OFF_IDX + TQ*CAP*2)
#define ATTN_SMEM (OFF_EXV + TQ*CAP*4)   // = 110912 bytes

__global__ __launch_bounds__(ATHREADS, 2)
void attn_kernel()
{
    extern __shared__ unsigned char smem[];
    unsigned short* s_sc = (unsigned short*)smem;             // [16][SROW]
    __nv_bfloat16* s_kb0 = (__nv_bfloat16*)(smem + OFF_KB0);  // [128][KROW]
    __nv_bfloat16* s_kb1 = (__nv_bfloat16*)(smem + OFF_KB1);  // [128][KROW]
    __nv_bfloat16* s_qb = (__nv_bfloat16*)(smem + OFF_QB);    // [16][64]
    int*   s_cnt = (int*)(smem + OFF_CNT);                    // [16]
    unsigned short* s_idx = (unsigned short*)(smem + OFF_IDX);// [16][CAP]
    float* s_exv = (float*)(smem + OFF_EXV);                  // [16][CAP]

    int bh = blockIdx.y;
    int q0 = blockIdx.x * TQ;
    const float* Q  = g_q  + ((size_t)bh * SS + q0) * DH;
    const float* KT = g_kT + (size_t)bh * DH * SS;
    const __nv_bfloat16* Kb = g_kb + (size_t)bh * SS * DH;
    const float* V  = g_v  + (size_t)bh * SS * DH;
    int tid = threadIdx.x;
    int lane = tid & 31, w = tid >> 5;

    // load Q tile bf16 copy
    for (int e = tid; e < TQ * DH; e += ATHREADS)
        s_qb[e] = __float2bfloat16(Q[e]);
    if (tid < TQ) s_cnt[tid] = 0;
    __syncthreads();

    const float scale = 0.125f;   // 1/sqrt(64)
    int r4 = lane >> 2, cq = (lane & 3) * 2;

    // A fragments (Q), persistent across chunks
    unsigned afr[4][4];
#pragma unroll
    for (int kk = 0; kk < 4; kk++) {
        int cb = kk * 16 + cq;
        afr[kk][0] = *(const unsigned*)&s_qb[ r4      * DH + cb    ];
        afr[kk][1] = *(const unsigned*)&s_qb[(r4 + 8) * DH + cb    ];
        afr[kk][2] = *(const unsigned*)&s_qb[ r4      * DH + cb + 8];
        afr[kk][3] = *(const unsigned*)&s_qb[(r4 + 8) * DH + cb + 8];
    }

    // staging lane geometry (2 float4 per thread per 128-row chunk)
    int row0 = tid >> 3,            c80 = tid & 7;
    int row1 = (tid + ATHREADS) >> 3, c81 = c80;

    // ---- phase 1: 16 chunks of 128 K-rows, double-buffered -----------------
    float4 rA0, rA1, rB0, rB1;
    // prologue: chunk 0 -> buf0; prefetch chunk 1
    rA0 = *(const float4*)(Kb + ((size_t)(row0)) * DH + c80 * 8);
    rA1 = *(const float4*)(Kb + ((size_t)(row1)) * DH + c81 * 8);
    *(float4*)((char*)s_kb0 + row0 * (KROW*2) + c80 * 16) = rA0;
    *(float4*)((char*)s_kb0 + row1 * (KROW*2) + c81 * 16) = rA1;
    rB0 = *(const float4*)(Kb + ((size_t)(128 + row0)) * DH + c80 * 8);
    rB1 = *(const float4*)(Kb + ((size_t)(128 + row1)) * DH + c81 * 8);
    __syncthreads();

#pragma unroll
    for (int ch = 0; ch < 16; ch += 2) {
        // even iter: mma buf0(ch); prefetch ch+2 -> A; commit B(ch+1) -> buf1
        if (ch + 2 < 16) {
            rA0 = *(const float4*)(Kb + ((size_t)((ch+2)*128 + row0)) * DH + c80 * 8);
            rA1 = *(const float4*)(Kb + ((size_t)((ch+2)*128 + row1)) * DH + c81 * 8);
        }
        {
            float c[4] = {0.f, 0.f, 0.f, 0.f};
            const __nv_bfloat16* kbp = s_kb0 + (w * 8 + r4) * KROW + cq;
#pragma unroll
            for (int kk = 0; kk < 4; kk++) {
                unsigned b0 = *(const unsigned*)(kbp + kk * 16);
                unsigned b1 = *(const unsigned*)(kbp + kk * 16 + 8);
                mma16816(c, afr[kk], b0, b1);
            }
            int n0 = ch * 128 + w * 8;
            __nv_bfloat162 lo = __floats2bfloat162_rn(c[0] * scale, c[1] * scale);
            __nv_bfloat162 hi = __floats2bfloat162_rn(c[2] * scale, c[3] * scale);
            *(__nv_bfloat162*)&s_sc[ r4      * SROW + n0 + cq] = lo;
            *(__nv_bfloat162*)&s_sc[(r4 + 8) * SROW + n0 + cq] = hi;
        }
        *(float4*)((char*)s_kb1 + row0 * (KROW*2) + c80 * 16) = rB0;
        *(float4*)((char*)s_kb1 + row1 * (KROW*2) + c81 * 16) = rB1;
        __syncthreads();

        // odd iter: mma buf1(ch+1); prefetch ch+3 -> B; commit A(ch+2) -> buf0
        if (ch + 3 < 16) {
            rB0 = *(const float4*)(Kb + ((size_t)((ch+3)*128 + row0)) * DH + c80 * 8);
            rB1 = *(const float4*)(Kb + ((size_t)((ch+3)*128 + row1)) * DH + c81 * 8);
        }
        {
            float c[4] = {0.f, 0.f, 0.f, 0.f};
            const __nv_bfloat16* kbp = s_kb1 + (w * 8 + r4) * KROW + cq;
#pragma unroll
            for (int kk = 0; kk < 4; kk++) {
                unsigned b0 = *(const unsigned*)(kbp + kk * 16);
                unsigned b1 = *(const unsigned*)(kbp + kk * 16 + 8);
                mma16816(c, afr[kk], b0, b1);
            }
            int n0 = (ch + 1) * 128 + w * 8;
            __nv_bfloat162 lo = __floats2bfloat162_rn(c[0] * scale, c[1] * scale);
            __nv_bfloat162 hi = __floats2bfloat162_rn(c[2] * scale, c[3] * scale);
            *(__nv_bfloat162*)&s_sc[ r4      * SROW + n0 + cq] = lo;
            *(__nv_bfloat162*)&s_sc[(r4 + 8) * SROW + n0 + cq] = hi;
        }
        if (ch + 2 < 16) {
            *(float4*)((char*)s_kb0 + row0 * (KROW*2) + c80 * 16) = rA0;
            *(float4*)((char*)s_kb0 + row1 * (KROW*2) + c81 * 16) = rA1;
        }
        __syncthreads();
    }

    // ---- phase 2: warp w owns row w ----------------------------------------
    const unsigned* scrow = (const unsigned*)(s_sc + w * SROW);  // 1024 u32

    float m = -3.0e38f;
#pragma unroll 8
    for (int jj = 0; jj < 32; jj++) {
        unsigned u = scrow[lane + (jj << 5)];
        m = fmaxf(m, fmaxf(bf16lo(u), bf16hi(u)));
    }
    m = warpMaxF(m);

    float thr = m - MARGIN;
    float z = 0.f, s1 = 0.f;
#pragma unroll 4
    for (int jj = 0; jj < 32; jj++) {
        int wi = lane + (jj << 5);
        unsigned u = scrow[wi];
        float a = bf16lo(u), bvv = bf16hi(u);
        float xa = a - m, xb = bvv - m;
        float pa = __expf(xa), pb = __expf(xb);
        z += pa + pb;
        s1 = fmaf(pa, xa, fmaf(pb, xb, s1));
        if (a >= thr) {
            int pos = atomicAdd(&s_cnt[w], 1);
            if (pos < CAP) s_idx[w * CAP + pos] = (unsigned short)(wi * 2);
        }
        if (bvv >= thr) {
            int pos = atomicAdd(&s_cnt[w], 1);
            if (pos < CAP) s_idx[w * CAP + pos] = (unsigned short)(wi * 2 + 1);
        }
    }
    z  = warpSumF(z);
    s1 = warpSumF(s1);
    float hent = logf(z) - s1 / z;   // approx entropy (tiny error, harmless)
    __syncwarp();
    int cnt = s_cnt[w];

    int b = bh >> 3, hd = bh & 7;
    float* outp = &g_attn[((size_t)(b * SS + q0 + w)) * DD + hd * DH + lane * 2];

    if (hent >= 1.2f && cnt <= CAP) {
        // rescue: exact fp32 scores for candidates; exact argmax + tie set
        const float* qrow = Q + w * DH;     // fp32 Q row (L2-resident)
        float q_lo = qrow[lane], q_hi = qrow[lane + 32];
        float m_ex = -3.0e38f;
        for (int t = 0; t < cnt; t++) {
            int j = s_idx[w * CAP + t];
            float part = fmaf(q_lo, KT[(size_t)lane * SS + j],
                              q_hi * KT[(size_t)(lane + 32) * SS + j]);
            float s = warpSumF(part) * scale;
            if (lane == 0) s_exv[w * CAP + t] = s;
            m_ex = fmaxf(m_ex, s);
        }
        __syncwarp();
        int tiec = 0;
        float a0 = 0.f, a1 = 0.f;
        int d0 = lane * 2;
        for (int t = 0; t < cnt; t++) {
            if (s_exv[w * CAP + t] == m_ex) {
                tiec++;
                int j = s_idx[w * CAP + t];
                float2 vv = *(const float2*)(V + (size_t)j * DH + d0);
                a0 += vv.x; a1 += vv.y;
            }
        }
        float wgt = 1.0f / ((float)tiec + EPSF * z);
        float2 o; o.x = a0 * wgt; o.y = a1 * wgt;
        *(float2*)outp = o;
    } else {
        // ---- cold exact fallback: full fp32 recompute, reference semantics -
        const float* qrow = Q + w * DH;
        float fb[64];
        for (int jj = 0; jj < 64; jj++) {
            int j = lane + (jj << 5);
            float s = 0.f;
            for (int d = 0; d < DH; d++)
                s = fmaf(qrow[d], KT[(size_t)d * SS + j], s);
            fb[jj] = s * scale;
        }
        float m2 = -3.0e38f;
        for (int jj = 0; jj < 64; jj++) m2 = fmaxf(m2, fb[jj]);
        m2 = warpMaxF(m2);
        float z2 = 0.f;
        for (int jj = 0; jj < 64; jj++) z2 += expf(fb[jj] - m2);
        z2 = warpSumF(z2);
        float invZ = 1.0f / z2;
        float he = 0.f;
        for (int jj = 0; jj < 64; jj++) {
            float p  = expf(fb[jj] - m2);
            float ww = p * invZ;
            he -= ww * logf(ww + EPSF);
        }
        he = warpSumF(he);
        int tk = (int)(32.0f * (1.0f - he));
        tk = tk < 1 ? 1 : (tk > MAXK ? MAXK : tk);

        unsigned thr_u;
        if (tk == 1) {
            thr_u = ordf(m2);
        } else {
            thr_u = 0xFFFFFFFFu;
            int removed = 0;
            while (removed < tk) {
                unsigned best = 0u;
                for (int jj = 0; jj < 64; jj++) {
                    unsigned u = ordf(fb[jj]);
                    if (u < thr_u && u > best) best = u;
                }
                best = warpMaxU(best);
                int c = 0;
                for (int jj = 0; jj < 64; jj++) c += (ordf(fb[jj]) == best);
                c = warpSumI(c);
                removed += c;
                thr_u = best;
            }
        }

        float P = 0.f;
        for (int jj = 0; jj < 64; jj++)
            if (ordf(fb[jj]) >= thr_u) P += expf(fb[jj] - m2);
        P = warpSumF(P);
        float invDen = 1.0f / (P + EPSF * z2);

        float r0 = 0.f, r1 = 0.f;
        for (int dd = 0; dd < DH; dd += 2) {
            float a0 = 0.f, a1 = 0.f;
            for (int jj = 0; jj < 64; jj++) {
                float s = fb[jj];
                if (ordf(s) >= thr_u) {
                    int j = lane + (jj << 5);
                    float p = expf(s - m2);
                    float2 vv = *(const float2*)(V + (size_t)j * DH + dd);
                    a0 = fmaf(p, vv.x, a0);
                    a1 = fmaf(p, vv.y, a1);
                }
            }
            a0 = warpSumF(a0);
            a1 = warpSumF(a1);
            if (lane == (dd >> 1)) { r0 = a0; r1 = a1; }
        }
        float2 o; o.x = r0 * invDen; o.y = r1 * invDen;
        *(float2*)outp = o;
    }
}

// ---------------- launch -----------------------------------------------------
extern "C" void kernel_launch(void* const* d_in, const int* in_sizes, int n_in,
                              void* d_out, int out_size)
{
    const float* x     = (const float*)d_in[0];
    const float* w_in  = (const float*)d_in[1];
    const float* b_in  = (const float*)d_in[2];
    const float* w_out = (const float*)d_in[3];
    const float* b_out = (const float*)d_in[4];
    float* out = (float*)d_out;

    float* pattn = nullptr;
    cudaGetSymbolAddress((void**)&pattn, g_attn);

    cudaFuncSetAttribute(attn_kernel,
                         cudaFuncAttributeMaxDynamicSharedMemorySize, ATTN_SMEM);

    // 1) QKV projection with head-layout scatter (768 blocks of 128x64)
    sgemm_nt<1><<<dim3((3*DD)/64, (BB*SS)/128), 256>>>(
        x, w_in, b_in, nullptr, BB*SS, 3*DD, DD);

    // 2) fused attention: pipelined smem-staged tensor-core scores
    attn_kernel<<<dim3(SS/TQ, BH), ATHREADS, ATTN_SMEM>>>();

    // 3) output projection (256 blocks of 128x64)
    sgemm_nt<0><<<dim3(DD/64, (BB*SS)/128), 256>>>(
        pattn, w_out, b_out, out, BB*SS, DD, DD);
}